// round 1
// baseline (speedup 1.0000x reference)
#include <cuda_runtime.h>

#define THREADS 256
typedef unsigned long long u64;

// Pre-transposed / pair-interleaved weight scratch (built once per launch by prep kernel)
__device__ float w1p_d[3 * 64 * 128 * 2];   // [l][c/2][h][2]  <- w1[l][h][c]
__device__ float gwp_d[64 * 256 * 2];       // [h/2][o][2]     <- grid_w[o][h]
__device__ float w2p_d[3 * 64 * 128 * 2];   // [l][h/2][c][2]  <- w2[l][c][h]

__device__ __forceinline__ u64 fma2(u64 a, u64 b, u64 c) {
    u64 d;
    asm("fma.rn.f32x2 %0, %1, %2, %3;" : "=l"(d) : "l"(a), "l"(b), "l"(c));
    return d;
}
__device__ __forceinline__ float hsum2(u64 v) {
    float a, b;
    asm("mov.b64 {%0, %1}, %2;" : "=f"(a), "=f"(b) : "l"(v));
    return a + b;
}

__global__ void prep_kernel(const float* __restrict__ w1,
                            const float* __restrict__ gw,
                            const float* __restrict__ w2) {
    int idx = blockIdx.x * THREADS + threadIdx.x;
    if (idx < 49152) {
        int l = idx >> 14, r = idx & 16383;
        int cp = r >> 8, r2 = r & 255, h = r2 >> 1, par = r2 & 1;
        w1p_d[idx] = w1[(l * 128 + h) * 128 + cp * 2 + par];
    } else if (idx < 81920) {
        int k = idx - 49152;
        int hp = k >> 9, r = k & 511, o = r >> 1, par = r & 1;
        gwp_d[k] = gw[o * 128 + hp * 2 + par];
    } else if (idx < 131072) {
        int k = idx - 81920;
        int l = k >> 14, r = k & 16383;
        int hp = r >> 8, r2 = r & 255, c = r2 >> 1, par = r2 & 1;
        w2p_d[k] = w2[(l * 128 + c) * 128 + hp * 2 + par];
    }
}

// One CTA per node, 256 threads. All intermediates in shared memory.
__global__ __launch_bounds__(256, 2) void fused_kernel(
    const float* __restrict__ x,
    const float* __restrict__ nw,
    const float* __restrict__ b1,
    const float* __restrict__ gb,
    const float* __restrict__ b2,
    const float* __restrict__ tg,
    const float* __restrict__ fg,
    float* __restrict__ y)
{
    extern __shared__ float sm[];
    float* sP   = sm;            // 1152: packed normalized input; reused later as h2
    float* sH   = sm + 1152;     // 1152: h1
    float* sG   = sm + 2304;     // 5376: grid g, then g2 (SwiGLU output)
    float* sZh  = sm + 7680;     // 5376: z high half staging
    float* s_tg = sm + 13056;    // 378
    float* s_fg = sm + 13434;    // 378
    float* s_nw = sm + 13812;    // 384
    float* s_gb = sm + 14196;    // 256
    float* s_b1 = sm + 14452;    // 128
    float* s_b2 = sm + 14580;    // 128
    float* sRed = sm + 14708;    // 8

    const int tid = threadIdx.x;
    const long long node = blockIdx.x;
    const float* xr = x + node * 1152;

    // stage small constants
    for (int j = tid; j < 378; j += THREADS) { s_tg[j] = tg[j]; s_fg[j] = fg[j]; }
    for (int j = tid; j < 384; j += THREADS) s_nw[j] = nw[j];
    s_gb[tid] = gb[tid];
    if (tid < 128) { s_b1[tid] = b1[tid]; s_b2[tid] = b2[tid]; }

    // ---- pack + sum of squares ----
    float ss = 0.f;
    for (int j = tid; j < 1152; j += THREADS) {
        float v = xr[j];
        ss += v * v;
        int m, c;
        if (j < 128)       { m = 0; c = j; }
        else if (j < 512)  { int u = j - 128; c = u / 3; m = 1 + (u - c * 3); }
        else               { int u = j - 512; c = u / 5; m = 4 + (u - c * 5); }
        sP[m * 128 + c] = v;
    }
    #pragma unroll
    for (int off = 16; off; off >>= 1) ss += __shfl_xor_sync(0xffffffffu, ss, off);
    if ((tid & 31) == 0) sRed[tid >> 5] = ss;
    __syncthreads();
    float tot = sRed[0] + sRed[1] + sRed[2] + sRed[3] +
                sRed[4] + sRed[5] + sRed[6] + sRed[7];
    float inv = 1.0f / sqrtf(tot * (1.0f / 1152.0f) + 1e-6f);
    for (int j = tid; j < 1152; j += THREADS) {
        int m = j >> 7, c = j & 127;
        int l = (m > 0) + (m > 3);
        sP[j] *= inv * s_nw[l * 128 + c];
    }
    __syncthreads();

    // ---- SO3Linear #1: h1[m][h] = sum_c p[m][c] * w1[l][h][c] ----
    {
        const int h = tid & 127;
        const int sel = tid >> 7;
        #pragma unroll
        for (int pass = 0; pass < 5; ++pass) {
            int m = pass * 2 + sel;
            if (m < 9) {
                int l = (m > 0) + (m > 3);
                const u64* wr = ((const u64*)w1p_d) + l * 8192 + h;  // stride 128 per cp
                const u64* pr = (const u64*)(sP + m * 128);
                u64 acc = 0ull;
                #pragma unroll 8
                for (int cp = 0; cp < 64; ++cp)
                    acc = fma2(pr[cp], wr[cp * 128], acc);
                float r = hsum2(acc);
                if (m == 0) r += s_b1[h];
                sH[m * 128 + h] = r;
            }
        }
    }
    __syncthreads();

    // ---- to S2 grid: g[a][h] = sum_m tg[a][m] * h1[m][h] ----
    for (int idx = tid; idx < 5376; idx += THREADS) {
        int a = idx >> 7, h = idx & 127;
        float acc = 0.f;
        #pragma unroll
        for (int m = 0; m < 9; ++m) acc += s_tg[a * 9 + m] * sH[m * 128 + h];
        sG[idx] = acc;
    }
    __syncthreads();

    // ---- SwiGLU GEMM: z[a][o] = sum_h g[a][h] * grid_w[o][h] + gb[o] ----
    float z[42];
    {
        const int o = tid;
        const u64* gwr = ((const u64*)gwp_d) + o;   // stride 256 per hp
        const u64* gp  = (const u64*)sG;            // [a*64 + hp] broadcast
        #pragma unroll
        for (int blk = 0; blk < 2; ++blk) {
            u64 acc[21];
            #pragma unroll
            for (int j = 0; j < 21; ++j) acc[j] = 0ull;
            #pragma unroll 2
            for (int hp = 0; hp < 64; ++hp) {
                u64 w = gwr[hp * 256];
                #pragma unroll
                for (int j = 0; j < 21; ++j)
                    acc[j] = fma2(gp[(blk * 21 + j) * 64 + hp], w, acc[j]);
            }
            #pragma unroll
            for (int j = 0; j < 21; ++j) z[blk * 21 + j] = hsum2(acc[j]) + s_gb[o];
        }
    }
    __syncthreads();
    if (tid >= 128) {
        int h = tid - 128;
        #pragma unroll
        for (int a = 0; a < 42; ++a) sZh[a * 128 + h] = z[a];
    }
    __syncthreads();
    if (tid < 128) {
        int h = tid;
        #pragma unroll
        for (int a = 0; a < 42; ++a) {
            float zl = z[a];
            float s = zl / (1.0f + __expf(-zl));       // silu
            sG[a * 128 + h] = s * sZh[a * 128 + h];    // g2 overwrites g
        }
    }
    __syncthreads();

    // ---- from S2 grid: h2[m][h] = sum_a fg[m][a] * g2[a][h]  (into sP) ----
    for (int idx = tid; idx < 1152; idx += THREADS) {
        int m = idx >> 7, h = idx & 127;
        float acc = 0.f;
        #pragma unroll
        for (int a = 0; a < 42; ++a) acc += s_fg[m * 42 + a] * sG[a * 128 + h];
        sP[idx] = acc;
    }
    __syncthreads();

    // ---- SO3Linear #2 + unpack store ----
    {
        const int c = tid & 127;
        const int sel = tid >> 7;
        float* yr = y + node * 1152;
        #pragma unroll
        for (int pass = 0; pass < 5; ++pass) {
            int m = pass * 2 + sel;
            if (m < 9) {
                int l = (m > 0) + (m > 3);
                const u64* wr = ((const u64*)w2p_d) + l * 8192 + c;  // stride 128 per hp
                const u64* hr = (const u64*)(sP + m * 128);
                u64 acc = 0ull;
                #pragma unroll 8
                for (int hp = 0; hp < 64; ++hp)
                    acc = fma2(hr[hp], wr[hp * 128], acc);
                float r = hsum2(acc);
                if (m == 0) r += s_b2[c];
                int pidx;
                if (m == 0)      pidx = c;
                else if (m < 4)  pidx = 128 + c * 3 + (m - 1);
                else             pidx = 512 + c * 5 + (m - 4);
                yr[pidx] = r;
            }
        }
    }
}

extern "C" void kernel_launch(void* const* d_in, const int* in_sizes, int n_in,
                              void* d_out, int out_size) {
    const float* x  = (const float*)d_in[0];
    const float* nw = (const float*)d_in[1];
    const float* w1 = (const float*)d_in[2];
    const float* b1 = (const float*)d_in[3];
    const float* gw = (const float*)d_in[4];
    const float* gb = (const float*)d_in[5];
    const float* w2 = (const float*)d_in[6];
    const float* b2 = (const float*)d_in[7];
    const float* tg = (const float*)d_in[8];
    const float* fg = (const float*)d_in[9];
    float* y = (float*)d_out;

    int N = in_sizes[0] / 1152;
    const int smem_bytes = 14716 * 4;  // 58864

    prep_kernel<<<512, THREADS>>>(w1, gw, w2);

    cudaFuncSetAttribute(fused_kernel, cudaFuncAttributeMaxDynamicSharedMemorySize,
                         smem_bytes);
    fused_kernel<<<N, THREADS, smem_bytes>>>(x, nw, b1, gb, b2, tg, fg, y);
}

// round 4
// speedup vs baseline: 1.0611x; 1.0611x over previous
#include <cuda_runtime.h>

#define THREADS 256
typedef unsigned long long u64;

// ---- prepped weight layouts (gmem scratch) ----
__device__ float w1q_d[3 * 32 * 128 * 4];   // [l][c4][h][4]  <- w1[l][h][c4*4+q]
__device__ float wT_d[128 * 256];           // [h][o]         <- grid_w[o][h]
__device__ float w2q_d[3 * 32 * 128 * 4];   // [l][h4][c][4]  <- w2[l][c][h4*4+q]

__device__ __forceinline__ u64 fma2(u64 a, u64 b, u64 c) {
    u64 d; asm("fma.rn.f32x2 %0, %1, %2, %3;" : "=l"(d) : "l"(a), "l"(b), "l"(c)); return d;
}
__device__ __forceinline__ u64 add2(u64 a, u64 b) {
    u64 d; asm("add.rn.f32x2 %0, %1, %2;" : "=l"(d) : "l"(a), "l"(b)); return d;
}
__device__ __forceinline__ u64 mul2(u64 a, u64 b) {
    u64 d; asm("mul.rn.f32x2 %0, %1, %2;" : "=l"(d) : "l"(a), "l"(b)); return d;
}
__device__ __forceinline__ u64 pk(float a, float b) {
    u64 r; asm("mov.b64 %0, {%1, %2};" : "=l"(r) : "f"(a), "f"(b)); return r;
}
__device__ __forceinline__ void up(u64 v, float& a, float& b) {
    asm("mov.b64 {%0, %1}, %2;" : "=f"(a), "=f"(b) : "l"(v));
}
__device__ __forceinline__ float hsum2(u64 v) { float a, b; up(v, a, b); return a + b; }

__global__ void prep_kernel(const float* __restrict__ w1,
                            const float* __restrict__ gw,
                            const float* __restrict__ w2) {
    int idx = blockIdx.x * THREADS + threadIdx.x;
    if (idx < 49152) {
        int l = idx >> 14, r = idx & 16383;
        int c4 = r >> 9, r2 = r & 511, h = r2 >> 2, q = r2 & 3;
        w1q_d[idx] = w1[(l * 128 + h) * 128 + c4 * 4 + q];
    } else if (idx < 81920) {
        int k = idx - 49152;
        int h = k >> 8, o = k & 255;
        wT_d[k] = gw[o * 128 + h];
    } else if (idx < 131072) {
        int k = idx - 81920;
        int l = k >> 14, r = k & 16383;
        int h4 = r >> 9, r2 = r & 511, c = r2 >> 2, q = r2 & 3;
        w2q_d[k] = w2[(l * 128 + c) * 128 + h4 * 4 + q];
    }
}

// smem float offsets
#define OFF_P    0        // 1152  packed/normalized p ; later h2
#define OFF_H    1152     // 1152  h1
#define OFF_GT   2304     // 6240  gT[h][48] (stride 48) ; later g2N[a][130]
#define OFF_SG   8544     // 6192  sg[a][129] silu(gate)
#define OFF_TG   14736    // 384
#define OFF_FG   15120    // 384
#define OFF_NW   15504    // 384
#define OFF_B1   15888    // 128
#define OFF_B2   16016    // 128
#define OFF_RED  16144    // 8
#define SMEM_FLOATS 16152

__global__ __launch_bounds__(256, 2) void fused_kernel(
    const float* __restrict__ x,
    const float* __restrict__ nw,
    const float* __restrict__ b1,
    const float* __restrict__ gb,
    const float* __restrict__ b2,
    const float* __restrict__ tg,
    const float* __restrict__ fg,
    float* __restrict__ y)
{
    extern __shared__ float sm[];
    float* sP   = sm + OFF_P;
    float* sH   = sm + OFF_H;
    float* gT   = sm + OFF_GT;   // [h][48]
    float* g2N  = sm + OFF_GT;   // [a][130] (alias, used after gT dead)
    float* sg   = sm + OFF_SG;   // [a][129]
    float* s_tg = sm + OFF_TG;
    float* s_fg = sm + OFF_FG;
    float* s_nw = sm + OFF_NW;
    float* s_b1 = sm + OFF_B1;
    float* s_b2 = sm + OFF_B2;
    float* sRed = sm + OFF_RED;

    const int tid = threadIdx.x;
    const long long node = blockIdx.x;
    const float* xr = x + node * 1152;

    // stage small constants
    for (int j = tid; j < 378; j += THREADS) { s_tg[j] = tg[j]; s_fg[j] = fg[j]; }
    for (int j = tid; j < 384; j += THREADS) s_nw[j] = nw[j];
    if (tid < 128) { s_b1[tid] = b1[tid]; s_b2[tid] = b2[tid]; }

    // ---- pack + sum of squares (vectorized x load) ----
    float ss = 0.f;
    {
        const float4* xr4 = (const float4*)xr;
        for (int j4 = tid; j4 < 288; j4 += THREADS) {
            float4 v4 = xr4[j4];
            int jb = j4 * 4;
            float vv[4] = {v4.x, v4.y, v4.z, v4.w};
            #pragma unroll
            for (int k = 0; k < 4; ++k) {
                int j = jb + k;
                float v = vv[k];
                ss += v * v;
                int m, c;
                if (j < 128)      { m = 0; c = j; }
                else if (j < 512) { int u = j - 128; c = u / 3; m = 1 + (u - c * 3); }
                else              { int u = j - 512; c = u / 5; m = 4 + (u - c * 5); }
                sP[m * 128 + c] = v;
            }
        }
    }
    #pragma unroll
    for (int off = 16; off; off >>= 1) ss += __shfl_xor_sync(0xffffffffu, ss, off);
    if ((tid & 31) == 0) sRed[tid >> 5] = ss;
    __syncthreads();
    {
        float tot = sRed[0] + sRed[1] + sRed[2] + sRed[3] +
                    sRed[4] + sRed[5] + sRed[6] + sRed[7];
        float inv = 1.0f / sqrtf(tot * (1.0f / 1152.0f) + 1e-6f);
        for (int j = tid; j < 1152; j += THREADS) {
            int m = j >> 7, c = j & 127;
            int l = (m > 0) + (m > 3);
            sP[j] *= inv * s_nw[l * 128 + c];
        }
    }
    __syncthreads();

    // ---- SO3Linear #1: h1[m][h] = sum_c p[m][c]*w1[l][h][c] ----
    {
        const int h = tid & 127;
        const int sel = tid >> 7;
        #pragma unroll
        for (int pass = 0; pass < 5; ++pass) {
            int m = pass * 2 + sel;
            if (m < 9) {
                int l = (m > 0) + (m > 3);
                const float4* wr = ((const float4*)w1q_d) + l * 4096 + h;  // +c4*128
                const float4* pr = (const float4*)(sP + m * 128);
                u64 a0 = 0ull, a1 = 0ull;
                #pragma unroll 8
                for (int c4 = 0; c4 < 32; ++c4) {
                    float4 w4 = wr[c4 * 128];
                    float4 p4 = pr[c4];
                    a0 = fma2(pk(p4.x, p4.y), pk(w4.x, w4.y), a0);
                    a1 = fma2(pk(p4.z, p4.w), pk(w4.z, w4.w), a1);
                }
                float r = hsum2(a0) + hsum2(a1);
                if (m == 0) r += s_b1[h];
                sH[m * 128 + h] = r;
            }
        }
    }
    __syncthreads();

    // ---- to S2 grid (f32x2 over h-pairs): gT[h][a] = sum_m tg[a][m]*h1[m][h] ----
    for (int idx = tid; idx < 2688; idx += THREADS) {
        int a = idx % 42;            // lanes consecutive in a -> conflict-free STS
        int hp = idx / 42;           // 0..63
        const u64* hr = ((const u64*)sH) + hp;   // + m*64
        u64 acc = 0ull;
        #pragma unroll
        for (int m = 0; m < 9; ++m) {
            float t = s_tg[a * 9 + m];
            acc = fma2(hr[m * 64], pk(t, t), acc);
        }
        float g0, g1; up(acc, g0, g1);
        gT[(2 * hp) * 48 + a]     = g0;
        gT[(2 * hp + 1) * 48 + a] = g1;
    }
    __syncthreads();

    // ---- SwiGLU GEMM, register-tiled outer product ----
    // CTA tile: 2 warp-rows (a) x 4 warp-cols (o). Thread: 6a x 8o.
    {
        const int wid = tid >> 5, lane = tid & 31;
        const int wa = wid >> 2, wo = wid & 3;
        const int ag = lane >> 3, og = lane & 7;
        const int a0 = wa * 24 + ag * 6;      // a in [0,48)
        const int o0 = wo * 64 + og * 8;      // o in [0,256)

        u64 acc[6][4];
        #pragma unroll
        for (int i = 0; i < 6; ++i)
            #pragma unroll
            for (int j = 0; j < 4; ++j) acc[i][j] = 0ull;

        const float4* wrow = ((const float4*)wT_d) + (o0 >> 2);  // + h*64
        const float* gbase = gT + a0;                             // + h*48

        #pragma unroll 2
        for (int h = 0; h < 128; ++h) {
            const u64* gp = (const u64*)(gbase + h * 48);
            u64 g01 = gp[0], g23 = gp[1], g45 = gp[2];
            float4 wA = wrow[h * 64];
            float4 wB = wrow[h * 64 + 1];
            u64 w0 = pk(wA.x, wA.y), w1v = pk(wA.z, wA.w);
            u64 w2v = pk(wB.x, wB.y), w3v = pk(wB.z, wB.w);
            float ga[6];
            up(g01, ga[0], ga[1]); up(g23, ga[2], ga[3]); up(g45, ga[4], ga[5]);
            #pragma unroll
            for (int i = 0; i < 6; ++i) {
                u64 gd = pk(ga[i], ga[i]);
                acc[i][0] = fma2(gd, w0, acc[i][0]);
                acc[i][1] = fma2(gd, w1v, acc[i][1]);
                acc[i][2] = fma2(gd, w2v, acc[i][2]);
                acc[i][3] = fma2(gd, w3v, acc[i][3]);
            }
        }

        // bias
        u64 gbp[4];
        {
            const u64* gb2 = ((const u64*)gb) + (o0 >> 1);
            #pragma unroll
            for (int j = 0; j < 4; ++j) gbp[j] = gb2[j];
        }
        #pragma unroll
        for (int i = 0; i < 6; ++i)
            #pragma unroll
            for (int j = 0; j < 4; ++j) acc[i][j] = add2(acc[i][j], gbp[j]);

        if (wo < 2) {
            // gate half: silu -> sg[a][129]
            #pragma unroll
            for (int i = 0; i < 6; ++i) {
                float* row = sg + (a0 + i) * 129 + o0;
                #pragma unroll
                for (int j = 0; j < 4; ++j) {
                    float z0, z1; up(acc[i][j], z0, z1);
                    row[2 * j]     = z0 / (1.0f + __expf(-z0));
                    row[2 * j + 1] = z1 / (1.0f + __expf(-z1));
                }
            }
        }
        __syncthreads();   // gT dead; sg ready
        if (wo >= 2) {
            const int hv = o0 - 128;
            #pragma unroll
            for (int i = 0; i < 6; ++i) {
                const float* srow = sg + (a0 + i) * 129 + hv;
                u64* drow = (u64*)(g2N + (a0 + i) * 130 + hv);
                #pragma unroll
                for (int j = 0; j < 4; ++j) {
                    u64 s2 = pk(srow[2 * j], srow[2 * j + 1]);
                    drow[j] = mul2(s2, acc[i][j]);
                }
            }
        }
    }
    __syncthreads();

    // ---- from S2 grid (f32x2 over h-pairs): h2[m][h] = sum_a fg[m][a]*g2[a][h] ----
    for (int idx = tid; idx < 576; idx += THREADS) {
        int m = idx / 64;
        int hp = idx % 64;
        const u64* g2 = ((const u64*)g2N) + hp;   // + a*65
        u64 acc = 0ull;
        #pragma unroll
        for (int a = 0; a < 42; ++a) {
            float f = s_fg[m * 42 + a];
            acc = fma2(g2[a * 65], pk(f, f), acc);
        }
        ((u64*)(sP + m * 128))[hp] = acc;
    }
    __syncthreads();

    // ---- SO3Linear #2 + unpack store ----
    {
        const int c = tid & 127;
        const int sel = tid >> 7;
        float* yr = y + node * 1152;
        #pragma unroll
        for (int pass = 0; pass < 5; ++pass) {
            int m = pass * 2 + sel;
            if (m < 9) {
                int l = (m > 0) + (m > 3);
                const float4* wr = ((const float4*)w2q_d) + l * 4096 + c;  // +h4*128
                const float4* hr = (const float4*)(sP + m * 128);
                u64 a0 = 0ull, a1 = 0ull;
                #pragma unroll 8
                for (int h4 = 0; h4 < 32; ++h4) {
                    float4 w4 = wr[h4 * 128];
                    float4 p4 = hr[h4];
                    a0 = fma2(pk(p4.x, p4.y), pk(w4.x, w4.y), a0);
                    a1 = fma2(pk(p4.z, p4.w), pk(w4.z, w4.w), a1);
                }
                float r = hsum2(a0) + hsum2(a1);
                if (m == 0) r += s_b2[c];
                int pidx;
                if (m == 0)      pidx = c;
                else if (m < 4)  pidx = 128 + c * 3 + (m - 1);
                else             pidx = 512 + c * 5 + (m - 4);
                yr[pidx] = r;
            }
        }
    }
}

extern "C" void kernel_launch(void* const* d_in, const int* in_sizes, int n_in,
                              void* d_out, int out_size) {
    const float* x  = (const float*)d_in[0];
    const float* nw = (const float*)d_in[1];
    const float* w1 = (const float*)d_in[2];
    const float* b1 = (const float*)d_in[3];
    const float* gw = (const float*)d_in[4];
    const float* gb = (const float*)d_in[5];
    const float* w2 = (const float*)d_in[6];
    const float* b2 = (const float*)d_in[7];
    const float* tg = (const float*)d_in[8];
    const float* fg = (const float*)d_in[9];
    float* y = (float*)d_out;

    int N = in_sizes[0] / 1152;
    const int smem_bytes = SMEM_FLOATS * 4;

    prep_kernel<<<512, THREADS>>>(w1, gw, w2);

    cudaFuncSetAttribute(fused_kernel, cudaFuncAttributeMaxDynamicSharedMemorySize,
                         smem_bytes);
    fused_kernel<<<N, THREADS, smem_bytes>>>(x, nw, b1, gb, b2, tg, fg, y);
}

// round 5
// speedup vs baseline: 1.3501x; 1.2724x over previous
#include <cuda_runtime.h>

#define THREADS 256
typedef unsigned long long u64;

// ---- prepped weight layouts (gmem scratch) ----
__device__ float w1q_d[3 * 32 * 128 * 4];   // [l][c4][h][4]  <- w1[l][h][c4*4+q]
__device__ float wT_d[128 * 256];           // [h][o]         <- grid_w[o][h]
__device__ float w2q_d[3 * 32 * 128 * 4];   // [l][h4][c][4]  <- w2[l][c][h4*4+q]

__device__ __forceinline__ u64 fma2(u64 a, u64 b, u64 c) {
    u64 d; asm("fma.rn.f32x2 %0, %1, %2, %3;" : "=l"(d) : "l"(a), "l"(b), "l"(c)); return d;
}
__device__ __forceinline__ u64 add2(u64 a, u64 b) {
    u64 d; asm("add.rn.f32x2 %0, %1, %2;" : "=l"(d) : "l"(a), "l"(b)); return d;
}
__device__ __forceinline__ u64 mul2(u64 a, u64 b) {
    u64 d; asm("mul.rn.f32x2 %0, %1, %2;" : "=l"(d) : "l"(a), "l"(b)); return d;
}
__device__ __forceinline__ u64 pk(float a, float b) {
    u64 r; asm("mov.b64 %0, {%1, %2};" : "=l"(r) : "f"(a), "f"(b)); return r;
}
__device__ __forceinline__ void up(u64 v, float& a, float& b) {
    asm("mov.b64 {%0, %1}, %2;" : "=f"(a), "=f"(b) : "l"(v));
}
__device__ __forceinline__ float hsum2(u64 v) { float a, b; up(v, a, b); return a + b; }

__global__ void prep_kernel(const float* __restrict__ w1,
                            const float* __restrict__ gw,
                            const float* __restrict__ w2) {
    int idx = blockIdx.x * THREADS + threadIdx.x;
    if (idx < 49152) {
        int l = idx >> 14, r = idx & 16383;
        int c4 = r >> 9, r2 = r & 511, h = r2 >> 2, q = r2 & 3;
        w1q_d[idx] = w1[(l * 128 + h) * 128 + c4 * 4 + q];
    } else if (idx < 81920) {
        int k = idx - 49152;
        int h = k >> 8, o = k & 255;
        wT_d[k] = gw[o * 128 + h];
    } else if (idx < 131072) {
        int k = idx - 81920;
        int l = k >> 14, r = k & 16383;
        int h4 = r >> 9, r2 = r & 511, c = r2 >> 2, q = r2 & 3;
        w2q_d[k] = w2[(l * 128 + c) * 128 + h4 * 4 + q];
    }
}

// ---- smem float offsets (NB = 4 nodes per CTA) ----
#define OFF_P    0        // 4x1152  packed/normalized p ; later h2
#define OFF_H    4608     // 4x1152  h1
#define OFF_GT   9216     // 6240    gT[h][48] ; later g2N[a][130]
#define OFF_SG   15456    // 6192    sg[a][129] silu(gate) ; later u64 partials
#define OFF_TGT  21648    // 504     tg padded [a][12]
#define OFF_FGT  22152    // 504     fg transposed padded [a][12]
#define OFF_NW   22656    // 384
#define OFF_B1   23040    // 128
#define OFF_B2   23168    // 128
#define OFF_RED  23296    // 32
#define SMEM_FLOATS 23328

// linear1 run: weights loaded once per c4, fanned over CNT m's x 4 nodes
template<int CNT, bool BIAS>
__device__ __forceinline__ void lin1_run(int l, int m0, int h,
        const float* sP, float* sH, const float* s_b1) {
    const float4* wr = ((const float4*)w1q_d) + l * 4096 + h;
    u64 a0[CNT][4], a1[CNT][4];
    #pragma unroll
    for (int i = 0; i < CNT; ++i)
        #pragma unroll
        for (int nb = 0; nb < 4; ++nb) { a0[i][nb] = 0ull; a1[i][nb] = 0ull; }
    #pragma unroll 2
    for (int c4 = 0; c4 < 32; ++c4) {
        float4 w4 = wr[c4 * 128];
        u64 wxy = pk(w4.x, w4.y), wzw = pk(w4.z, w4.w);
        #pragma unroll
        for (int i = 0; i < CNT; ++i) {
            #pragma unroll
            for (int nb = 0; nb < 4; ++nb) {
                float4 p4 = ((const float4*)(sP + nb * 1152 + (m0 + i) * 128))[c4];
                a0[i][nb] = fma2(pk(p4.x, p4.y), wxy, a0[i][nb]);
                a1[i][nb] = fma2(pk(p4.z, p4.w), wzw, a1[i][nb]);
            }
        }
    }
    #pragma unroll
    for (int i = 0; i < CNT; ++i)
        #pragma unroll
        for (int nb = 0; nb < 4; ++nb) {
            float r = hsum2(a0[i][nb]) + hsum2(a1[i][nb]);
            if (BIAS) r += s_b1[h];
            sH[nb * 1152 + (m0 + i) * 128 + h] = r;
        }
}

// linear2 run: same structure, writes unpacked directly to gmem
template<int CNT, bool BIAS>
__device__ __forceinline__ void lin2_run(int l, int m0, int c,
        const float* sP, const float* s_b2,
        float* __restrict__ y, long long n0, int Nn) {
    const float4* wr = ((const float4*)w2q_d) + l * 4096 + c;
    u64 a0[CNT][4], a1[CNT][4];
    #pragma unroll
    for (int i = 0; i < CNT; ++i)
        #pragma unroll
        for (int nb = 0; nb < 4; ++nb) { a0[i][nb] = 0ull; a1[i][nb] = 0ull; }
    #pragma unroll 2
    for (int h4 = 0; h4 < 32; ++h4) {
        float4 w4 = wr[h4 * 128];
        u64 wxy = pk(w4.x, w4.y), wzw = pk(w4.z, w4.w);
        #pragma unroll
        for (int i = 0; i < CNT; ++i) {
            #pragma unroll
            for (int nb = 0; nb < 4; ++nb) {
                float4 p4 = ((const float4*)(sP + nb * 1152 + (m0 + i) * 128))[h4];
                a0[i][nb] = fma2(pk(p4.x, p4.y), wxy, a0[i][nb]);
                a1[i][nb] = fma2(pk(p4.z, p4.w), wzw, a1[i][nb]);
            }
        }
    }
    #pragma unroll
    for (int i = 0; i < CNT; ++i) {
        int m = m0 + i;
        int pidx;
        if (m == 0)      pidx = c;
        else if (m < 4)  pidx = 128 + c * 3 + (m - 1);
        else             pidx = 512 + c * 5 + (m - 4);
        #pragma unroll
        for (int nb = 0; nb < 4; ++nb) {
            float r = hsum2(a0[i][nb]) + hsum2(a1[i][nb]);
            if (BIAS) r += s_b2[c];
            long long node = n0 + nb; if (node >= Nn) node = Nn - 1;
            y[node * 1152 + pidx] = r;
        }
    }
}

__global__ __launch_bounds__(256, 2) void fused_kernel(
    const float* __restrict__ x,
    const float* __restrict__ nw,
    const float* __restrict__ b1,
    const float* __restrict__ gb,
    const float* __restrict__ b2,
    const float* __restrict__ tg,
    const float* __restrict__ fg,
    float* __restrict__ y, int Nn)
{
    extern __shared__ float sm[];
    float* sP    = sm + OFF_P;
    float* sH    = sm + OFF_H;
    float* gT    = sm + OFF_GT;   // [h][48]
    float* g2N   = sm + OFF_GT;   // [a][130] alias
    float* sg    = sm + OFF_SG;   // [a][129] ; later u64 partials
    float* s_tgT = sm + OFF_TGT;
    float* s_fgT = sm + OFF_FGT;
    float* s_nw  = sm + OFF_NW;
    float* s_b1  = sm + OFF_B1;
    float* s_b2  = sm + OFF_B2;
    float* sRed  = sm + OFF_RED;

    const int tid = threadIdx.x;
    const long long n0 = (long long)blockIdx.x * 4;

    // stage small constants (padded [a][12] layouts for vector loads)
    for (int j = tid; j < 378; j += THREADS) {
        int a = j / 9, m = j - a * 9;
        s_tgT[a * 12 + m] = tg[j];            // tg is [a][m]
        s_fgT[a * 12 + m] = fg[m * 42 + a];   // fg is [m][a] -> transpose
    }
    for (int j = tid; j < 384; j += THREADS) s_nw[j] = nw[j];
    if (tid < 128) { s_b1[tid] = b1[tid]; s_b2[tid] = b2[tid]; }

    // ---- pack + sum of squares, 4 nodes ----
    float ss[4] = {0.f, 0.f, 0.f, 0.f};
    #pragma unroll
    for (int nb = 0; nb < 4; ++nb) {
        long long node = n0 + nb; if (node >= Nn) node = Nn - 1;
        const float4* xr4 = (const float4*)(x + node * 1152);
        float* sPn = sP + nb * 1152;
        for (int j4 = tid; j4 < 288; j4 += THREADS) {
            float4 v4 = xr4[j4];
            int jb = j4 * 4;
            float vv[4] = {v4.x, v4.y, v4.z, v4.w};
            #pragma unroll
            for (int k = 0; k < 4; ++k) {
                int j = jb + k;
                float v = vv[k];
                ss[nb] += v * v;
                int m, c;
                if (j < 128)      { m = 0; c = j; }
                else if (j < 512) { int u = j - 128; c = u / 3; m = 1 + (u - c * 3); }
                else              { int u = j - 512; c = u / 5; m = 4 + (u - c * 5); }
                sPn[m * 128 + c] = v;
            }
        }
    }
    #pragma unroll
    for (int nb = 0; nb < 4; ++nb) {
        float s = ss[nb];
        #pragma unroll
        for (int off = 16; off; off >>= 1) s += __shfl_xor_sync(0xffffffffu, s, off);
        if ((tid & 31) == 0) sRed[nb * 8 + (tid >> 5)] = s;
    }
    __syncthreads();
    {
        float inv[4];
        #pragma unroll
        for (int nb = 0; nb < 4; ++nb) {
            float tot = 0.f;
            #pragma unroll
            for (int w = 0; w < 8; ++w) tot += sRed[nb * 8 + w];
            inv[nb] = 1.0f / sqrtf(tot * (1.0f / 1152.0f) + 1e-6f);
        }
        for (int j = tid; j < 1152; j += THREADS) {
            int m = j >> 7, c = j & 127;
            int l = (m > 0) + (m > 3);
            float s = s_nw[l * 128 + c];
            #pragma unroll
            for (int nb = 0; nb < 4; ++nb) sP[nb * 1152 + j] *= inv[nb] * s;
        }
    }
    __syncthreads();

    // ---- SO3Linear #1, l-grouped, 4-node batched ----
    {
        const int h = tid & 127;
        if (tid < 128) {
            lin1_run<1, true >(0, 0, h, sP, sH, s_b1);
            lin1_run<3, false>(2, 4, h, sP, sH, s_b1);
        } else {
            lin1_run<3, false>(1, 1, h, sP, sH, s_b1);
            lin1_run<2, false>(2, 7, h, sP, sH, s_b1);
        }
    }
    __syncthreads();

    // ---- per-node grid pipeline ----
    for (int nb = 0; nb < 4; ++nb) {
        const float* sHn = sH + nb * 1152;
        float* sPn = sP + nb * 1152;

        // -- to S2 grid: thread owns fixed a, tg in registers, streams h1 pairs --
        if (tid < 252) {
            int a = tid % 42, hp0 = tid / 42;
            const float4* tgp = (const float4*)(s_tgT + a * 12);
            float4 f0 = tgp[0], f1 = tgp[1];
            float f8 = s_tgT[a * 12 + 8];
            float tr[9] = {f0.x, f0.y, f0.z, f0.w, f1.x, f1.y, f1.z, f1.w, f8};
            const u64* hr0 = (const u64*)sHn;
            for (int hp = hp0; hp < 64; hp += 6) {
                const u64* hr = hr0 + hp;
                u64 acc = 0ull;
                #pragma unroll
                for (int m = 0; m < 9; ++m)
                    acc = fma2(hr[m * 64], pk(tr[m], tr[m]), acc);
                float g0, g1; up(acc, g0, g1);
                gT[(2 * hp) * 48 + a]     = g0;
                gT[(2 * hp + 1) * 48 + a] = g1;
            }
        }
        __syncthreads();

        // -- SwiGLU GEMM, register-tiled outer product (2x4 warps, 6a x 8o / thread) --
        {
            const int wid = tid >> 5, lane = tid & 31;
            const int wa = wid >> 2, wo = wid & 3;
            const int ag = lane >> 3, og = lane & 7;
            const int a0 = wa * 24 + ag * 6;
            const int o0 = wo * 64 + og * 8;

            u64 acc[6][4];
            #pragma unroll
            for (int i = 0; i < 6; ++i)
                #pragma unroll
                for (int j = 0; j < 4; ++j) acc[i][j] = 0ull;

            const float4* wrow = ((const float4*)wT_d) + (o0 >> 2);
            const float* gbase = gT + a0;

            #pragma unroll 2
            for (int h = 0; h < 128; ++h) {
                const u64* gp = (const u64*)(gbase + h * 48);
                u64 g01 = gp[0], g23 = gp[1], g45 = gp[2];
                float4 wA = wrow[h * 64];
                float4 wB = wrow[h * 64 + 1];
                u64 w0 = pk(wA.x, wA.y), w1v = pk(wA.z, wA.w);
                u64 w2v = pk(wB.x, wB.y), w3v = pk(wB.z, wB.w);
                float ga[6];
                up(g01, ga[0], ga[1]); up(g23, ga[2], ga[3]); up(g45, ga[4], ga[5]);
                #pragma unroll
                for (int i = 0; i < 6; ++i) {
                    u64 gd = pk(ga[i], ga[i]);
                    acc[i][0] = fma2(gd, w0, acc[i][0]);
                    acc[i][1] = fma2(gd, w1v, acc[i][1]);
                    acc[i][2] = fma2(gd, w2v, acc[i][2]);
                    acc[i][3] = fma2(gd, w3v, acc[i][3]);
                }
            }

            u64 gbp[4];
            {
                const u64* gb2 = ((const u64*)gb) + (o0 >> 1);
                #pragma unroll
                for (int j = 0; j < 4; ++j) gbp[j] = gb2[j];
            }
            #pragma unroll
            for (int i = 0; i < 6; ++i)
                #pragma unroll
                for (int j = 0; j < 4; ++j) acc[i][j] = add2(acc[i][j], gbp[j]);

            if (wo < 2) {
                #pragma unroll
                for (int i = 0; i < 6; ++i) {
                    float* row = sg + (a0 + i) * 129 + o0;
                    #pragma unroll
                    for (int j = 0; j < 4; ++j) {
                        float z0, z1; up(acc[i][j], z0, z1);
                        row[2 * j]     = z0 / (1.0f + __expf(-z0));
                        row[2 * j + 1] = z1 / (1.0f + __expf(-z1));
                    }
                }
            }
            __syncthreads();   // gT dead; sg ready
            if (wo >= 2) {
                const int hv = o0 - 128;
                #pragma unroll
                for (int i = 0; i < 6; ++i) {
                    const float* srow = sg + (a0 + i) * 129 + hv;
                    u64* drow = (u64*)(g2N + (a0 + i) * 130 + hv);
                    #pragma unroll
                    for (int j = 0; j < 4; ++j) {
                        u64 s2 = pk(srow[2 * j], srow[2 * j + 1]);
                        drow[j] = mul2(s2, acc[i][j]);
                    }
                }
            }
        }
        __syncthreads();

        // -- from S2 grid, phase 1: thread owns hp, stream g2 once over a-chunk --
        {
            const int hp = tid & 63, chunk = tid >> 6;
            const int abeg = (chunk == 0) ? 0 : (chunk == 1) ? 11 : (chunk == 2) ? 22 : 32;
            const int aend = (chunk == 0) ? 11 : (chunk == 1) ? 22 : (chunk == 2) ? 32 : 42;
            u64 am[9];
            #pragma unroll
            for (int m = 0; m < 9; ++m) am[m] = 0ull;
            const u64* g2 = ((const u64*)g2N) + hp;
            for (int a = abeg; a < aend; ++a) {
                u64 g = g2[a * 65];
                const float4* fp = (const float4*)(s_fgT + a * 12);
                float4 q0 = fp[0], q1 = fp[1];
                float q8 = s_fgT[a * 12 + 8];
                float fr[9] = {q0.x, q0.y, q0.z, q0.w, q1.x, q1.y, q1.z, q1.w, q8};
                #pragma unroll
                for (int m = 0; m < 9; ++m)
                    am[m] = fma2(g, pk(fr[m], fr[m]), am[m]);
            }
            u64* part = (u64*)sg;   // sg dead
            #pragma unroll
            for (int m = 0; m < 9; ++m)
                part[(chunk * 9 + m) * 64 + hp] = am[m];
        }
        __syncthreads();
        // -- phase 2: reduce 4 partials -> h2 into sP[nb] --
        {
            const u64* part = (const u64*)sg;
            for (int idx = tid; idx < 576; idx += THREADS) {
                int m = idx >> 6, hp = idx & 63;
                u64 s = add2(add2(part[(0 + m) * 64 + hp], part[(9 + m) * 64 + hp]),
                             add2(part[(18 + m) * 64 + hp], part[(27 + m) * 64 + hp]));
                ((u64*)(sPn + m * 128))[hp] = s;
            }
        }
        __syncthreads();
    }

    // ---- SO3Linear #2 + unpack store, l-grouped, 4-node batched ----
    {
        const int c = tid & 127;
        if (tid < 128) {
            lin2_run<1, true >(0, 0, c, sP, s_b2, y, n0, Nn);
            lin2_run<3, false>(2, 4, c, sP, s_b2, y, n0, Nn);
        } else {
            lin2_run<3, false>(1, 1, c, sP, s_b2, y, n0, Nn);
            lin2_run<2, false>(2, 7, c, sP, s_b2, y, n0, Nn);
        }
    }
}

extern "C" void kernel_launch(void* const* d_in, const int* in_sizes, int n_in,
                              void* d_out, int out_size) {
    const float* x  = (const float*)d_in[0];
    const float* nw = (const float*)d_in[1];
    const float* w1 = (const float*)d_in[2];
    const float* b1 = (const float*)d_in[3];
    const float* gw = (const float*)d_in[4];
    const float* gb = (const float*)d_in[5];
    const float* w2 = (const float*)d_in[6];
    const float* b2 = (const float*)d_in[7];
    const float* tg = (const float*)d_in[8];
    const float* fg = (const float*)d_in[9];
    float* y = (float*)d_out;

    int N = in_sizes[0] / 1152;
    int nblk = (N + 3) / 4;
    const int smem_bytes = SMEM_FLOATS * 4;

    prep_kernel<<<512, THREADS>>>(w1, gw, w2);

    cudaFuncSetAttribute(fused_kernel, cudaFuncAttributeMaxDynamicSharedMemorySize,
                         smem_bytes);
    fused_kernel<<<nblk, THREADS, smem_bytes>>>(x, nw, b1, gb, b2, tg, fg, y, N);
}